// round 7
// baseline (speedup 1.0000x reference)
#include <cuda_runtime.h>
#include <cstdint>

// Model_39676907886975: fused attention, fp32, shapes (256,32,16,64).
//   attn = softmax(q @ k^T / sqrt(8) + 1), dropout(p=0.3, JAX partitionable
//   threefry key=(0,42)), out = attn @ v.
// R6: all FMAs packed as fma.rn.f32x2 (2 MACs/issue), ps stored as duplicated
// (p,p) u64 pairs, packed accumulators stored via 128-bit STG.

#define ROTL32(x, r) (((x) << (r)) | ((x) >> (32 - (r))))

__device__ __forceinline__ uint32_t tf_bits_0_42(uint32_t idx) {
    // JAX partitionable threefry: (o0,o1) = threefry2x32((0,42),(0,idx)); o0^o1
    uint32_t x0 = 0u, x1 = idx;
    const uint32_t ks0 = 0u;
    const uint32_t ks1 = 42u;
    const uint32_t ks2 = 0x1BD11BDAu ^ ks0 ^ ks1;
    x0 += ks0; x1 += ks1;
#define TF_R4(a, b, c, d)                       \
    x0 += x1; x1 = ROTL32(x1, a); x1 ^= x0;     \
    x0 += x1; x1 = ROTL32(x1, b); x1 ^= x0;     \
    x0 += x1; x1 = ROTL32(x1, c); x1 ^= x0;     \
    x0 += x1; x1 = ROTL32(x1, d); x1 ^= x0;
    TF_R4(13, 15, 26, 6)   x0 += ks1; x1 += ks2 + 1u;
    TF_R4(17, 29, 16, 24)  x0 += ks2; x1 += ks0 + 2u;
    TF_R4(13, 15, 26, 6)   x0 += ks0; x1 += ks1 + 3u;
    TF_R4(17, 29, 16, 24)  x0 += ks1; x1 += ks2 + 4u;
    TF_R4(13, 15, 26, 6)   x0 += ks2; x1 += ks0 + 5u;
#undef TF_R4
    return x0 ^ x1;
}

__device__ __forceinline__ float drop_scale(uint32_t idx) {
    uint32_t bits = tf_bits_0_42(idx);
    float u = __uint_as_float((bits >> 9) | 0x3F800000u) - 1.0f;
    return (u < 0.7f) ? (1.0f / 0.7f) : 0.0f;
}

// ---- packed fp32x2 helpers (Blackwell FFMA2) ----
__device__ __forceinline__ unsigned long long fma2(
    unsigned long long a, unsigned long long b, unsigned long long c) {
    unsigned long long d;
    asm("fma.rn.f32x2 %0, %1, %2, %3;" : "=l"(d) : "l"(a), "l"(b), "l"(c));
    return d;
}
__device__ __forceinline__ unsigned long long pack2(float x, float y) {
    unsigned long long r;
    asm("mov.b64 %0, {%1, %2};" : "=l"(r) : "f"(x), "f"(y));
    return r;
}
__device__ __forceinline__ float hadd2(unsigned long long a) {
    float lo, hi;
    asm("mov.b64 {%0, %1}, %2;" : "=f"(lo), "=f"(hi) : "l"(a));
    return lo + hi;
}

__global__ __launch_bounds__(128) void attn_fused_kernel(
    const float* __restrict__ q,
    const float* __restrict__ k,
    const float* __restrict__ v,
    float* __restrict__ out)
{
    // 2 bh per CTA; 64 threads per bh. Row stride 17 float4 (odd super-bank
    // stride) keeps 8-distinct-row LDS.128 reads conflict-free.
    __shared__ float4 qs[2][16][17];
    __shared__ float4 ks[2][16][17];
    __shared__ float4 vs[2][16][16];
    __shared__ unsigned long long ps[2][16][17];   // ps[g][t][s] = (p,p) packed

    const int tid   = threadIdx.x;
    const int g     = tid >> 6;        // bh sub-index 0..1
    const int local = tid & 63;
    const int bh    = blockIdx.x * 2 + g;
    const int wb    = local >> 5;      // s-half
    const int lane  = local & 31;
    const int sb    = lane >> 3;       // 0..3
    const int tb    = lane & 7;        // 0..7
    const int s0 = wb * 8 + sb, s1 = s0 + 4;
    const int t0 = tb,          t1 = tb + 8;

    const size_t base_f4 = (size_t)bh * 256u;  // 16*64 floats = 256 float4
    const float4* q4 = reinterpret_cast<const float4*>(q) + base_f4;
    const float4* k4 = reinterpret_cast<const float4*>(k) + base_f4;
    const float4* v4 = reinterpret_cast<const float4*>(v) + base_f4;

    // ---- stage tiles (coalesced float4) ----
#pragma unroll
    for (int j = 0; j < 4; ++j) {
        int idx = local + 64 * j;
        int r = idx >> 4, c = idx & 15;
        qs[g][r][c] = q4[idx];
        ks[g][r][c] = k4[idx];
        vs[g][r][c] = v4[idx];
    }
    __syncthreads();

    // ---- logits: 2x2 block per thread, packed f32x2 accumulation ----
    unsigned long long c00 = 0ull, c01 = 0ull, c10 = 0ull, c11 = 0ull;
#pragma unroll
    for (int i = 0; i < 16; ++i) {
        ulonglong2 A0 = *reinterpret_cast<const ulonglong2*>(&qs[g][s0][i]);
        ulonglong2 A1 = *reinterpret_cast<const ulonglong2*>(&qs[g][s1][i]);
        ulonglong2 B0 = *reinterpret_cast<const ulonglong2*>(&ks[g][t0][i]);
        ulonglong2 B1 = *reinterpret_cast<const ulonglong2*>(&ks[g][t1][i]);
        c00 = fma2(A0.x, B0.x, c00); c00 = fma2(A0.y, B0.y, c00);
        c01 = fma2(A0.x, B1.x, c01); c01 = fma2(A0.y, B1.y, c01);
        c10 = fma2(A1.x, B0.x, c10); c10 = fma2(A1.y, B0.y, c10);
        c11 = fma2(A1.x, B1.x, c11); c11 = fma2(A1.y, B1.y, c11);
    }
    const float SCALE = 0.35355339059327373f;   // 1/sqrt(8)
    // exp without max-subtraction: |logit| <~ 20 for N(0,1) inputs, safe fp32
    float e00 = __expf(fmaf(hadd2(c00), SCALE, 1.0f));
    float e01 = __expf(fmaf(hadd2(c01), SCALE, 1.0f));
    float e10 = __expf(fmaf(hadd2(c10), SCALE, 1.0f));
    float e11 = __expf(fmaf(hadd2(c11), SCALE, 1.0f));

    // row sums over the 8-lane tb group
    float r0 = e00 + e01;
    float r1 = e10 + e11;
#pragma unroll
    for (int off = 1; off <= 4; off <<= 1) {
        r0 += __shfl_xor_sync(0xFFFFFFFFu, r0, off, 8);
        r1 += __shfl_xor_sync(0xFFFFFFFFu, r1, off, 8);
    }
    float inv0 = 1.0f / r0, inv1 = 1.0f / r1;

    // ---- dropout (JAX partitionable threefry, flat attn index) ----
    uint32_t ib = (uint32_t)bh * 256u;
    float p00 = e00 * inv0 * drop_scale(ib + s0 * 16 + t0);
    float p01 = e01 * inv0 * drop_scale(ib + s0 * 16 + t1);
    float p10 = e10 * inv1 * drop_scale(ib + s1 * 16 + t0);
    float p11 = e11 * inv1 * drop_scale(ib + s1 * 16 + t1);

    // store duplicated pairs: reader's packed multiplier needs no pack op
    ps[g][t0][s0] = pack2(p00, p00);
    ps[g][t1][s0] = pack2(p01, p01);
    ps[g][t0][s1] = pack2(p10, p10);
    ps[g][t1][s1] = pack2(p11, p11);
    __syncthreads();

    // ---- PV: 2x2 block, packed accumulators ----
    unsigned long long oxy00 = 0ull, ozw00 = 0ull, oxy01 = 0ull, ozw01 = 0ull;
    unsigned long long oxy10 = 0ull, ozw10 = 0ull, oxy11 = 0ull, ozw11 = 0ull;
#pragma unroll
    for (int t = 0; t < 16; ++t) {
        unsigned long long w0 = ps[g][t][s0];
        unsigned long long w1 = ps[g][t][s1];
        ulonglong2 V0 = *reinterpret_cast<const ulonglong2*>(&vs[g][t][t0]);
        ulonglong2 V1 = *reinterpret_cast<const ulonglong2*>(&vs[g][t][t1]);
        oxy00 = fma2(w0, V0.x, oxy00); ozw00 = fma2(w0, V0.y, ozw00);
        oxy01 = fma2(w0, V1.x, oxy01); ozw01 = fma2(w0, V1.y, ozw01);
        oxy10 = fma2(w1, V0.x, oxy10); ozw10 = fma2(w1, V0.y, ozw10);
        oxy11 = fma2(w1, V1.x, oxy11); ozw11 = fma2(w1, V1.y, ozw11);
    }

    ulonglong2* o2 = reinterpret_cast<ulonglong2*>(out) + base_f4;
    o2[s0 * 16 + t0] = make_ulonglong2(oxy00, ozw00);
    o2[s0 * 16 + t1] = make_ulonglong2(oxy01, ozw01);
    o2[s1 * 16 + t0] = make_ulonglong2(oxy10, ozw10);
    o2[s1 * 16 + t1] = make_ulonglong2(oxy11, ozw11);
}

extern "C" void kernel_launch(void* const* d_in, const int* in_sizes, int n_in,
                              void* d_out, int out_size)
{
    const float* q = (const float*)d_in[0];
    const float* k = (const float*)d_in[1];
    const float* v = (const float*)d_in[2];
    float* out = (float*)d_out;
    // B*H = 8192 bh; 2 bh per CTA
    attn_fused_kernel<<<4096, 128>>>(q, k, v, out);
}